// round 3
// baseline (speedup 1.0000x reference)
#include <cuda_runtime.h>

#define N_NODES 100000
#define N_EDGES 1000000
#define N_GRAPHS 128

typedef unsigned long long u64t;

// ---------------- packed f32x2 helpers (Blackwell FFMA2 path) ---------------
__device__ __forceinline__ u64t ffma2(u64t a, u64t b, u64t c) {
    u64t d;
    asm("fma.rn.f32x2 %0, %1, %2, %3;" : "=l"(d) : "l"(a), "l"(b), "l"(c));
    return d;
}
__device__ __forceinline__ u64t add2(u64t a, u64t b) {
    u64t d;
    asm("add.rn.f32x2 %0, %1, %2;" : "=l"(d) : "l"(a), "l"(b));
    return d;
}
__device__ __forceinline__ u64t pack2(float lo, float hi) {
    u64t r;
    asm("mov.b64 %0, {%1, %2};" : "=l"(r) : "f"(lo), "f"(hi));
    return r;
}
__device__ __forceinline__ float2 unpack2(u64t v) {
    float2 r;
    asm("mov.b64 {%0, %1}, %2;" : "=f"(r.x), "=f"(r.y) : "l"(v));
    return r;
}

// ---------------- scratch (static device globals; allocation-free) ----------
__device__ __align__(16) float g_aggr[N_NODES * 64];
__device__ __align__(16) float g_h1[N_NODES * 64];
__device__ __align__(16) float g_pool[N_GRAPHS * 64];

// ---------------- aggr = (1+eps) * x  (conv1 only) ---------------------------
__global__ __launch_bounds__(256) void k_init(const float4* __restrict__ x,
                                              const float* __restrict__ eps,
                                              float4* __restrict__ aggr) {
    int i = blockIdx.x * blockDim.x + threadIdx.x;
    float s = 1.0f + *eps;
    float4 v = x[i];
    v.x *= s; v.y *= s; v.z *= s; v.w *= s;
    aggr[i] = v;
}

// ---------------- edge kernel: m = relu(x[src] + ea@We + be); aggr[dst]+=m --
// 64 edges x 64 cols per 256-thread block; f32x2 packed FMA mainloop.
__global__ __launch_bounds__(256) void k_edge(const float4* __restrict__ x4,
                                              const float4* __restrict__ ea4,
                                              const int* __restrict__ src,
                                              const int* __restrict__ dst,
                                              const float4* __restrict__ We4,
                                              const float4* __restrict__ be4,
                                              float4* __restrict__ aggr4) {
    __shared__ u64t       sEA[64][33];   // {a,a} replicated pairs, padded
    __shared__ ulonglong2 sW[32][16];    // cols packed: .x={c0,c1} .y={c2,c3}
    __shared__ int        sDst[64];

    const int tid = threadIdx.x;
    const int e0  = blockIdx.x * 64;
    const int cg  = tid & 15;
    const int eg  = tid >> 4;

    // early gather (latency hides behind staging + FMA loop)
    int myS[4];
#pragma unroll
    for (int i = 0; i < 4; i++) myS[i] = __ldg(&src[e0 + eg * 4 + i]);
    float4 xv[4];
#pragma unroll
    for (int i = 0; i < 4; i++) xv[i] = __ldg(&x4[(size_t)myS[i] * 16 + cg]);

    // stage We packed
    for (int i = tid; i < 512; i += 256) {
        float4 v = We4[i];
        sW[i >> 4][i & 15] = make_ulonglong2(pack2(v.x, v.y), pack2(v.z, v.w));
    }
    if (tid < 64) sDst[tid] = dst[e0 + tid];
    // stage edge attrs as replicated pairs
    for (int i = tid; i < 512; i += 256) {
        int e = i >> 3, q = i & 7;
        float4 v = ea4[(size_t)(e0 + e) * 8 + q];
        sEA[e][q * 4 + 0] = pack2(v.x, v.x);
        sEA[e][q * 4 + 1] = pack2(v.y, v.y);
        sEA[e][q * 4 + 2] = pack2(v.z, v.z);
        sEA[e][q * 4 + 3] = pack2(v.w, v.w);
    }
    __syncthreads();

    float4 bv = __ldg(&be4[cg]);
    u64t accL[4], accH[4];
#pragma unroll
    for (int i = 0; i < 4; i++) { accL[i] = pack2(bv.x, bv.y); accH[i] = pack2(bv.z, bv.w); }

#pragma unroll
    for (int k = 0; k < 32; k++) {
        ulonglong2 w = sW[k][cg];
#pragma unroll
        for (int i = 0; i < 4; i++) {
            u64t aa = sEA[eg * 4 + i][k];
            accL[i] = ffma2(aa, w.x, accL[i]);
            accH[i] = ffma2(aa, w.y, accH[i]);
        }
    }

#pragma unroll
    for (int i = 0; i < 4; i++) {
        int d = sDst[eg * 4 + i];
        u64t l = add2(accL[i], pack2(xv[i].x, xv[i].y));
        u64t h = add2(accH[i], pack2(xv[i].z, xv[i].w));
        float2 lo = unpack2(l), hi = unpack2(h);
        float4 m;
        m.x = fmaxf(lo.x, 0.0f);
        m.y = fmaxf(lo.y, 0.0f);
        m.z = fmaxf(hi.x, 0.0f);
        m.w = fmaxf(hi.y, 0.0f);
        atomicAdd(&aggr4[(size_t)d * 16 + cg], m);  // RED.E.128
    }
}

// ---------------- node MLP: hout = relu( relu(hin@W1+b1) @ W2 + b2 ) --------
// 32 nodes / 256 threads; f32x2 packed FMA.
// POOL=false: writes hout AND aggr_next = (1+eps_next)*hout   (fuses k_init#2)
// POOL=true : atomically adds hout into pool[batch[n]]
template <bool POOL>
__global__ __launch_bounds__(256) void k_mlp(const float* __restrict__ hin,
                                             const float4* __restrict__ W1_4,
                                             const float4* __restrict__ b1_4,
                                             const float4* __restrict__ W2_4,
                                             const float4* __restrict__ b2_4,
                                             float4* __restrict__ hout4,
                                             const float* __restrict__ eps_next,
                                             float4* __restrict__ aggr_next,
                                             const int* __restrict__ batch,
                                             float4* __restrict__ pool4) {
    __shared__ ulonglong2 sW1[64][16];   // 16 KB
    __shared__ ulonglong2 sW2[64][16];   // 16 KB
    __shared__ float      sH[32][64];    // 8 KB
    __shared__ float4     sT[32][16];    // 8 KB

    const int tid = threadIdx.x;
    const int n0  = blockIdx.x * 32;

    for (int i = tid; i < 1024; i += 256) {
        float4 v1 = W1_4[i];
        float4 v2 = W2_4[i];
        sW1[i >> 4][i & 15] = make_ulonglong2(pack2(v1.x, v1.y), pack2(v1.z, v1.w));
        sW2[i >> 4][i & 15] = make_ulonglong2(pack2(v2.x, v2.y), pack2(v2.z, v2.w));
    }
    for (int i = tid; i < 32 * 64; i += 256) {
        int n = i >> 6, k = i & 63;
        sH[n][k] = hin[(size_t)(n0 + n) * 64 + k];
    }
    __syncthreads();

    const int cg = tid & 15;
    const int ng = tid >> 4;
    const int na = ng * 2, nb = ng * 2 + 1;
    const float* sTf = (const float*)sT;

    // layer 1
    float4 b1 = __ldg(&b1_4[cg]);
    u64t a0L = pack2(b1.x, b1.y), a0H = pack2(b1.z, b1.w);
    u64t a1L = a0L, a1H = a0H;
#pragma unroll
    for (int k = 0; k < 64; k++) {
        ulonglong2 w = sW1[k][cg];
        u64t ha = pack2(sH[na][k], sH[na][k]);
        u64t hb = pack2(sH[nb][k], sH[nb][k]);
        a0L = ffma2(ha, w.x, a0L); a0H = ffma2(ha, w.y, a0H);
        a1L = ffma2(hb, w.x, a1L); a1H = ffma2(hb, w.y, a1H);
    }
    {
        float2 l0 = unpack2(a0L), h0 = unpack2(a0H);
        float2 l1 = unpack2(a1L), h1v = unpack2(a1H);
        float4 t0, t1;
        t0.x = fmaxf(l0.x, 0.0f); t0.y = fmaxf(l0.y, 0.0f);
        t0.z = fmaxf(h0.x, 0.0f); t0.w = fmaxf(h0.y, 0.0f);
        t1.x = fmaxf(l1.x, 0.0f); t1.y = fmaxf(l1.y, 0.0f);
        t1.z = fmaxf(h1v.x, 0.0f); t1.w = fmaxf(h1v.y, 0.0f);
        sT[na][cg] = t0;
        sT[nb][cg] = t1;
    }
    __syncthreads();

    // layer 2 (+ outer relu of the conv)
    float4 b2 = __ldg(&b2_4[cg]);
    u64t c0L = pack2(b2.x, b2.y), c0H = pack2(b2.z, b2.w);
    u64t c1L = c0L, c1H = c0H;
#pragma unroll
    for (int k = 0; k < 64; k++) {
        ulonglong2 w = sW2[k][cg];
        u64t ta = pack2(sTf[na * 64 + k], sTf[na * 64 + k]);
        u64t tb = pack2(sTf[nb * 64 + k], sTf[nb * 64 + k]);
        c0L = ffma2(ta, w.x, c0L); c0H = ffma2(ta, w.y, c0H);
        c1L = ffma2(tb, w.x, c1L); c1H = ffma2(tb, w.y, c1H);
    }
    float2 l0 = unpack2(c0L), h0 = unpack2(c0H);
    float2 l1 = unpack2(c1L), h1v = unpack2(c1H);
    float4 o0, o1;
    o0.x = fmaxf(l0.x, 0.0f); o0.y = fmaxf(l0.y, 0.0f);
    o0.z = fmaxf(h0.x, 0.0f); o0.w = fmaxf(h0.y, 0.0f);
    o1.x = fmaxf(l1.x, 0.0f); o1.y = fmaxf(l1.y, 0.0f);
    o1.z = fmaxf(h1v.x, 0.0f); o1.w = fmaxf(h1v.y, 0.0f);

    if (POOL) {
        int ba = __ldg(&batch[n0 + na]);
        int bb = __ldg(&batch[n0 + nb]);
        atomicAdd(&pool4[(size_t)ba * 16 + cg], o0);
        atomicAdd(&pool4[(size_t)bb * 16 + cg], o1);
    } else {
        hout4[(size_t)(n0 + na) * 16 + cg] = o0;
        hout4[(size_t)(n0 + nb) * 16 + cg] = o1;
        float s = 1.0f + __ldg(eps_next);
        float4 z0, z1;
        z0.x = s * o0.x; z0.y = s * o0.y; z0.z = s * o0.z; z0.w = s * o0.w;
        z1.x = s * o1.x; z1.y = s * o1.y; z1.z = s * o1.z; z1.w = s * o1.w;
        aggr_next[(size_t)(n0 + na) * 16 + cg] = z0;
        aggr_next[(size_t)(n0 + nb) * 16 + cg] = z1;
    }
}

// ---------------- head: out = relu(pool@Wf1+bf1) @ Wf2 + bf2 ----------------
__global__ __launch_bounds__(128) void k_head(const float* __restrict__ pool,
                                              const float* __restrict__ Wf1,
                                              const float* __restrict__ bf1,
                                              const float* __restrict__ Wf2,
                                              const float* __restrict__ bf2,
                                              float* __restrict__ out) {
    __shared__ float sW[64][128];
    const int tid = threadIdx.x;
    for (int i = tid; i < 64 * 128; i += 128) sW[i >> 7][i & 127] = Wf1[i];
    __syncthreads();

    float p[64];
#pragma unroll
    for (int k = 0; k < 64; k++) p[k] = pool[tid * 64 + k];

    float o = 0.0f;
    for (int j = 0; j < 128; j++) {
        float s = bf1[j];
#pragma unroll
        for (int k = 0; k < 64; k++) s = fmaf(p[k], sW[k][j], s);
        o = fmaf(fmaxf(s, 0.0f), Wf2[j], o);
    }
    out[tid] = o + bf2[0];
}

// ---------------- launch --------------------------------------------------
extern "C" void kernel_launch(void* const* d_in, const int* in_sizes, int n_in,
                              void* d_out, int out_size) {
    const float* x    = (const float*)d_in[0];
    const float* ea   = (const float*)d_in[1];
    const int*   src  = (const int*)d_in[2];
    const int*   dst  = (const int*)d_in[3];
    const int*   bat  = (const int*)d_in[4];
    const float* eps1 = (const float*)d_in[5];
    const float* We1  = (const float*)d_in[6];
    const float* be1  = (const float*)d_in[7];
    const float* W11  = (const float*)d_in[8];
    const float* b11  = (const float*)d_in[9];
    const float* W12  = (const float*)d_in[10];
    const float* b12  = (const float*)d_in[11];
    const float* eps2 = (const float*)d_in[12];
    const float* We2  = (const float*)d_in[13];
    const float* be2  = (const float*)d_in[14];
    const float* W21  = (const float*)d_in[15];
    const float* b21  = (const float*)d_in[16];
    const float* W22  = (const float*)d_in[17];
    const float* b22  = (const float*)d_in[18];
    const float* Wf1  = (const float*)d_in[19];
    const float* bf1  = (const float*)d_in[20];
    const float* Wf2  = (const float*)d_in[21];
    const float* bf2  = (const float*)d_in[22];

    void *aggr_p, *h1_p, *pool_p;
    cudaGetSymbolAddress(&aggr_p, g_aggr);
    cudaGetSymbolAddress(&h1_p, g_h1);
    cudaGetSymbolAddress(&pool_p, g_pool);
    float4* aggr4 = (float4*)aggr_p;
    float*  aggr  = (float*)aggr_p;
    float4* h1_4  = (float4*)h1_p;
    float*  h1    = (float*)h1_p;
    float4* pool4 = (float4*)pool_p;
    float*  pool  = (float*)pool_p;

    const int INIT_BLOCKS = (N_NODES * 16) / 256;   // 6250
    const int EDGE_BLOCKS = N_EDGES / 64;           // 15625
    const int MLP_BLOCKS  = N_NODES / 32;           // 3125

    cudaMemsetAsync(pool_p, 0, N_GRAPHS * 64 * sizeof(float));

    // ---- conv1 ----
    k_init<<<INIT_BLOCKS, 256>>>((const float4*)x, eps1, aggr4);
    k_edge<<<EDGE_BLOCKS, 256>>>((const float4*)x, (const float4*)ea, src, dst,
                                 (const float4*)We1, (const float4*)be1, aggr4);
    // writes h1 and aggr = (1+eps2)*h1 (init for conv2 fused)
    k_mlp<false><<<MLP_BLOCKS, 256>>>(aggr, (const float4*)W11, (const float4*)b11,
                                      (const float4*)W12, (const float4*)b12,
                                      h1_4, eps2, aggr4, nullptr, nullptr);
    // ---- conv2 ----
    k_edge<<<EDGE_BLOCKS, 256>>>((const float4*)h1, (const float4*)ea, src, dst,
                                 (const float4*)We2, (const float4*)be2, aggr4);
    k_mlp<true><<<MLP_BLOCKS, 256>>>(aggr, (const float4*)W21, (const float4*)b21,
                                     (const float4*)W22, (const float4*)b22,
                                     nullptr, nullptr, nullptr, bat, pool4);
    // ---- head ----
    k_head<<<1, 128>>>(pool, Wf1, bf1, Wf2, bf2, (float*)d_out);
}

// round 4
// speedup vs baseline: 1.2004x; 1.2004x over previous
#include <cuda_runtime.h>

#define N_NODES 100000
#define N_EDGES 1000000
#define N_GRAPHS 128

typedef unsigned long long u64t;

// ---------------- packed f32x2 helpers --------------------------------------
__device__ __forceinline__ u64t ffma2(u64t a, u64t b, u64t c) {
    u64t d;
    asm("fma.rn.f32x2 %0, %1, %2, %3;" : "=l"(d) : "l"(a), "l"(b), "l"(c));
    return d;
}
__device__ __forceinline__ u64t pack2(float lo, float hi) {
    u64t r;
    asm("mov.b64 %0, {%1, %2};" : "=l"(r) : "f"(lo), "f"(hi));
    return r;
}
__device__ __forceinline__ float2 unpack2(u64t v) {
    float2 r;
    asm("mov.b64 {%0, %1}, %2;" : "=f"(r.x), "=f"(r.y) : "l"(v));
    return r;
}
// weight-pair slot permutation: thread cg reads slots {2cg,2cg+1,16+2cg,16+2cg+1}
// (two aligned ulonglong2 loads, conflict-free) = pairs {4cg,4cg+1,4cg+2,4cg+3}.
__device__ __forceinline__ int wslot(int p) {
    return (p & 1) | (((p >> 2) & 7) << 1) | (((p >> 1) & 1) << 4);
}

// ---------------- scratch ----------------------------------------------------
__device__ __align__(16) float g_aggr[N_NODES * 64];
__device__ __align__(16) float g_h1[N_NODES * 64];
__device__ __align__(16) float g_pool[N_GRAPHS * 64];

// ---------------- aggr = (1+eps1) * x ---------------------------------------
__global__ __launch_bounds__(256) void k_init(const float4* __restrict__ x,
                                              const float* __restrict__ eps,
                                              float4* __restrict__ aggr) {
    int i = blockIdx.x * blockDim.x + threadIdx.x;
    float s = 1.0f + *eps;
    float4 v = x[i];
    v.x *= s; v.y *= s; v.z *= s; v.w *= s;
    aggr[i] = v;
}

// ---------------- edge kernel ------------------------------------------------
// 160 edges x 64 cols per 160-thread block. Thread tile: 8 edges x 8 cols
// (outer product, 32 u64 accumulators). Weights 2x LDS.128/k, ea 1x LDS.128
// per edge per 4-k chunk (swizzled, broadcast, conflict-free).
#define EPB 160
__global__ void __launch_bounds__(160, 3)
k_edge(const float4* __restrict__ x4,
       const float4* __restrict__ ea4,
       const int* __restrict__ src,
       const int* __restrict__ dst,
       const float4* __restrict__ We4,
       const float4* __restrict__ be4,
       float4* __restrict__ aggr4) {
    __shared__ float4 sEA4[EPB * 9];   // [e][9] float4; chunk q stored at q^((e>>3)&3)
    __shared__ u64t   sW[32][32];      // [k][slot]
    __shared__ int    sDst[EPB];

    const int tid   = threadIdx.x;
    const int e0    = blockIdx.x * EPB;
    const int cg    = tid & 7;          // 8 col-groups (8 cols = pairs 4cg..4cg+3)
    const int eg    = tid >> 3;         // 20 edge-groups of 8
    const int ebase = eg * 8;

    // early: own src indices (latency hidden behind staging + mainloop)
    int mySrc[8];
#pragma unroll
    for (int i = 0; i < 8; i++) mySrc[i] = __ldg(&src[e0 + ebase + i]);

    // stage We [32][64] -> permuted u64 pairs
    for (int i = tid; i < 512; i += EPB) {
        int k = i >> 4, c4 = i & 15;
        float4 v = We4[i];
        sW[k][wslot(c4 * 2)]     = pack2(v.x, v.y);
        sW[k][wslot(c4 * 2 + 1)] = pack2(v.z, v.w);
    }
    // stage ea with xor swizzle on the float4-chunk index
#pragma unroll
    for (int i = tid; i < EPB * 8; i += EPB) {
        int e = i >> 3, q = i & 7;
        sEA4[e * 9 + (q ^ ((e >> 3) & 3))] = ea4[(size_t)(e0 + e) * 8 + q];
    }
    if (tid < EPB) sDst[tid] = dst[e0 + tid];
    __syncthreads();

    // bias -> 4 col pairs, replicated into 8x4 accumulators
    float4 b0 = __ldg(&be4[cg * 2]);
    float4 b1 = __ldg(&be4[cg * 2 + 1]);
    u64t bias[4] = { pack2(b0.x, b0.y), pack2(b0.z, b0.w),
                     pack2(b1.x, b1.y), pack2(b1.z, b1.w) };
    u64t acc[8][4];
#pragma unroll
    for (int i = 0; i < 8; i++)
#pragma unroll
        for (int j = 0; j < 4; j++) acc[i][j] = bias[j];

    const int sw = eg & 3;
#pragma unroll
    for (int k4 = 0; k4 < 8; k4++) {
        float4 eav[8];
#pragma unroll
        for (int i = 0; i < 8; i++)
            eav[i] = sEA4[(ebase + i) * 9 + (k4 ^ sw)];
#pragma unroll
        for (int kk = 0; kk < 4; kk++) {
            int k = k4 * 4 + kk;
            ulonglong2 wA = *(const ulonglong2*)&sW[k][2 * cg];
            ulonglong2 wB = *(const ulonglong2*)&sW[k][16 + 2 * cg];
#pragma unroll
            for (int i = 0; i < 8; i++) {
                float a = (kk == 0) ? eav[i].x : (kk == 1) ? eav[i].y
                        : (kk == 2) ? eav[i].z : eav[i].w;
                u64t aa = pack2(a, a);
                acc[i][0] = ffma2(aa, wA.x, acc[i][0]);
                acc[i][1] = ffma2(aa, wA.y, acc[i][1]);
                acc[i][2] = ffma2(aa, wB.x, acc[i][2]);
                acc[i][3] = ffma2(aa, wB.y, acc[i][3]);
            }
        }
    }

    // epilogue: gather x[src], relu(acc+x), scatter-add. 2-deep pipeline.
    const int col0 = cg * 2, col1 = cg * 2 + 1;
    float4 xa[2], xb[2];
    xa[0] = __ldg(&x4[(size_t)mySrc[0] * 16 + col0]);
    xb[0] = __ldg(&x4[(size_t)mySrc[0] * 16 + col1]);
    xa[1] = __ldg(&x4[(size_t)mySrc[1] * 16 + col0]);
    xb[1] = __ldg(&x4[(size_t)mySrc[1] * 16 + col1]);
#pragma unroll
    for (int e = 0; e < 8; e++) {
        float4 xva = xa[e & 1], xvb = xb[e & 1];
        if (e + 2 < 8) {
            xa[e & 1] = __ldg(&x4[(size_t)mySrc[e + 2] * 16 + col0]);
            xb[e & 1] = __ldg(&x4[(size_t)mySrc[e + 2] * 16 + col1]);
        }
        float2 v0 = unpack2(acc[e][0]);
        float2 v1 = unpack2(acc[e][1]);
        float2 v2 = unpack2(acc[e][2]);
        float2 v3 = unpack2(acc[e][3]);
        float4 m0, m1;
        m0.x = fmaxf(v0.x + xva.x, 0.0f);
        m0.y = fmaxf(v0.y + xva.y, 0.0f);
        m0.z = fmaxf(v1.x + xva.z, 0.0f);
        m0.w = fmaxf(v1.y + xva.w, 0.0f);
        m1.x = fmaxf(v2.x + xvb.x, 0.0f);
        m1.y = fmaxf(v2.y + xvb.y, 0.0f);
        m1.z = fmaxf(v3.x + xvb.z, 0.0f);
        m1.w = fmaxf(v3.y + xvb.w, 0.0f);
        int d = sDst[ebase + e];
        atomicAdd(&aggr4[(size_t)d * 16 + col0], m0);
        atomicAdd(&aggr4[(size_t)d * 16 + col1], m1);
    }
}

// ---------------- node MLP ---------------------------------------------------
// 128 nodes per 256-thread block; thread tile 4 nodes x 8 cols.
// Dynamic smem: sW1 (16KB) + sW2 (16KB) + sHT[64][132] (33.8KB, reused for T).
#define MLP_NPB 128
#define MLP_SMEM (64 * 32 * 8 * 2 + 64 * 132 * 4)
template <bool POOL>
__global__ void __launch_bounds__(256, 2)
k_mlp(const float4* __restrict__ hin4,
      const float4* __restrict__ W1_4,
      const float4* __restrict__ b1_4,
      const float4* __restrict__ W2_4,
      const float4* __restrict__ b2_4,
      float4* __restrict__ hout4,
      const float* __restrict__ eps_next,
      float4* __restrict__ aggr_next,
      const int* __restrict__ batch,
      float4* __restrict__ pool4) {
    extern __shared__ char smem_raw[];
    u64t*  sW1 = (u64t*)smem_raw;                 // [64][32]
    u64t*  sW2 = sW1 + 64 * 32;                   // [64][32]
    float* sHT = (float*)(sW2 + 64 * 32);         // [64][132] transposed acts

    const int tid = threadIdx.x;
    const int n0  = blockIdx.x * MLP_NPB;
    const int cg  = tid & 7;                      // 8 col-groups
    const int ng  = tid >> 3;                     // 32 node-groups of 4

    // stage weights
    for (int i = tid; i < 1024; i += 256) {
        int k = i >> 4, c4 = i & 15;
        float4 v1 = W1_4[i];
        float4 v2 = W2_4[i];
        sW1[k * 32 + wslot(c4 * 2)]     = pack2(v1.x, v1.y);
        sW1[k * 32 + wslot(c4 * 2 + 1)] = pack2(v1.z, v1.w);
        sW2[k * 32 + wslot(c4 * 2)]     = pack2(v2.x, v2.y);
        sW2[k * 32 + wslot(c4 * 2 + 1)] = pack2(v2.z, v2.w);
    }
    // stage h transposed: sHT[k][n]
    for (int i = tid; i < MLP_NPB * 16; i += 256) {
        int n = i & 127, k4 = i >> 7;
        float4 v = (n0 + n < N_NODES) ? hin4[(size_t)(n0 + n) * 16 + k4]
                                      : make_float4(0.f, 0.f, 0.f, 0.f);
        sHT[(4 * k4 + 0) * 132 + n] = v.x;
        sHT[(4 * k4 + 1) * 132 + n] = v.y;
        sHT[(4 * k4 + 2) * 132 + n] = v.z;
        sHT[(4 * k4 + 3) * 132 + n] = v.w;
    }
    __syncthreads();

    // ---- layer 1 ----
    float4 c0 = __ldg(&b1_4[cg * 2]);
    float4 c1 = __ldg(&b1_4[cg * 2 + 1]);
    u64t bias1[4] = { pack2(c0.x, c0.y), pack2(c0.z, c0.w),
                      pack2(c1.x, c1.y), pack2(c1.z, c1.w) };
    u64t acc[4][4];
#pragma unroll
    for (int n = 0; n < 4; n++)
#pragma unroll
        for (int j = 0; j < 4; j++) acc[n][j] = bias1[j];

#pragma unroll 8
    for (int k = 0; k < 64; k++) {
        float4 hv = *(const float4*)&sHT[k * 132 + ng * 4];
        ulonglong2 wA = *(const ulonglong2*)&sW1[k * 32 + 2 * cg];
        ulonglong2 wB = *(const ulonglong2*)&sW1[k * 32 + 16 + 2 * cg];
#pragma unroll
        for (int n = 0; n < 4; n++) {
            float h = (n == 0) ? hv.x : (n == 1) ? hv.y : (n == 2) ? hv.z : hv.w;
            u64t hh = pack2(h, h);
            acc[n][0] = ffma2(hh, wA.x, acc[n][0]);
            acc[n][1] = ffma2(hh, wA.y, acc[n][1]);
            acc[n][2] = ffma2(hh, wB.x, acc[n][2]);
            acc[n][3] = ffma2(hh, wB.y, acc[n][3]);
        }
    }
    __syncthreads();   // all sHT reads done; safe to overwrite with t
#pragma unroll
    for (int n = 0; n < 4; n++) {
#pragma unroll
        for (int j = 0; j < 4; j++) {
            float2 v = unpack2(acc[n][j]);
            int col = 8 * cg + 2 * j;
            sHT[(col)     * 132 + ng * 4 + n] = fmaxf(v.x, 0.0f);
            sHT[(col + 1) * 132 + ng * 4 + n] = fmaxf(v.y, 0.0f);
        }
    }
    __syncthreads();

    // ---- layer 2 ----
    float4 d0 = __ldg(&b2_4[cg * 2]);
    float4 d1 = __ldg(&b2_4[cg * 2 + 1]);
    u64t bias2[4] = { pack2(d0.x, d0.y), pack2(d0.z, d0.w),
                      pack2(d1.x, d1.y), pack2(d1.z, d1.w) };
#pragma unroll
    for (int n = 0; n < 4; n++)
#pragma unroll
        for (int j = 0; j < 4; j++) acc[n][j] = bias2[j];

#pragma unroll 8
    for (int k = 0; k < 64; k++) {
        float4 hv = *(const float4*)&sHT[k * 132 + ng * 4];
        ulonglong2 wA = *(const ulonglong2*)&sW2[k * 32 + 2 * cg];
        ulonglong2 wB = *(const ulonglong2*)&sW2[k * 32 + 16 + 2 * cg];
#pragma unroll
        for (int n = 0; n < 4; n++) {
            float h = (n == 0) ? hv.x : (n == 1) ? hv.y : (n == 2) ? hv.z : hv.w;
            u64t hh = pack2(h, h);
            acc[n][0] = ffma2(hh, wA.x, acc[n][0]);
            acc[n][1] = ffma2(hh, wA.y, acc[n][1]);
            acc[n][2] = ffma2(hh, wB.x, acc[n][2]);
            acc[n][3] = ffma2(hh, wB.y, acc[n][3]);
        }
    }

    // ---- epilogue ----
    const int col0 = cg * 2, col1 = cg * 2 + 1;
    float s = POOL ? 0.0f : (1.0f + __ldg(eps_next));
#pragma unroll
    for (int n = 0; n < 4; n++) {
        int node = n0 + ng * 4 + n;
        if (node >= N_NODES) break;
        float2 v0 = unpack2(acc[n][0]);
        float2 v1 = unpack2(acc[n][1]);
        float2 v2 = unpack2(acc[n][2]);
        float2 v3 = unpack2(acc[n][3]);
        float4 o0, o1;
        o0.x = fmaxf(v0.x, 0.0f); o0.y = fmaxf(v0.y, 0.0f);
        o0.z = fmaxf(v1.x, 0.0f); o0.w = fmaxf(v1.y, 0.0f);
        o1.x = fmaxf(v2.x, 0.0f); o1.y = fmaxf(v2.y, 0.0f);
        o1.z = fmaxf(v3.x, 0.0f); o1.w = fmaxf(v3.y, 0.0f);
        if (POOL) {
            int b = __ldg(&batch[node]);
            atomicAdd(&pool4[(size_t)b * 16 + col0], o0);
            atomicAdd(&pool4[(size_t)b * 16 + col1], o1);
        } else {
            hout4[(size_t)node * 16 + col0] = o0;
            hout4[(size_t)node * 16 + col1] = o1;
            float4 z0, z1;
            z0.x = s * o0.x; z0.y = s * o0.y; z0.z = s * o0.z; z0.w = s * o0.w;
            z1.x = s * o1.x; z1.y = s * o1.y; z1.z = s * o1.z; z1.w = s * o1.w;
            aggr_next[(size_t)node * 16 + col0] = z0;
            aggr_next[(size_t)node * 16 + col1] = z1;
        }
    }
}

// ---------------- head -------------------------------------------------------
__global__ __launch_bounds__(128) void k_head(const float* __restrict__ pool,
                                              const float* __restrict__ Wf1,
                                              const float* __restrict__ bf1,
                                              const float* __restrict__ Wf2,
                                              const float* __restrict__ bf2,
                                              float* __restrict__ out) {
    __shared__ float sW[64][128];
    const int tid = threadIdx.x;
    for (int i = tid; i < 64 * 128; i += 128) sW[i >> 7][i & 127] = Wf1[i];
    __syncthreads();

    float p[64];
#pragma unroll
    for (int k = 0; k < 64; k++) p[k] = pool[tid * 64 + k];

    float o = 0.0f;
    for (int j = 0; j < 128; j++) {
        float s = bf1[j];
#pragma unroll
        for (int k = 0; k < 64; k++) s = fmaf(p[k], sW[k][j], s);
        o = fmaf(fmaxf(s, 0.0f), Wf2[j], o);
    }
    out[tid] = o + bf2[0];
}

// ---------------- launch -----------------------------------------------------
extern "C" void kernel_launch(void* const* d_in, const int* in_sizes, int n_in,
                              void* d_out, int out_size) {
    const float* x    = (const float*)d_in[0];
    const float* ea   = (const float*)d_in[1];
    const int*   src  = (const int*)d_in[2];
    const int*   dst  = (const int*)d_in[3];
    const int*   bat  = (const int*)d_in[4];
    const float* eps1 = (const float*)d_in[5];
    const float* We1  = (const float*)d_in[6];
    const float* be1  = (const float*)d_in[7];
    const float* W11  = (const float*)d_in[8];
    const float* b11  = (const float*)d_in[9];
    const float* W12  = (const float*)d_in[10];
    const float* b12  = (const float*)d_in[11];
    const float* eps2 = (const float*)d_in[12];
    const float* We2  = (const float*)d_in[13];
    const float* be2  = (const float*)d_in[14];
    const float* W21  = (const float*)d_in[15];
    const float* b21  = (const float*)d_in[16];
    const float* W22  = (const float*)d_in[17];
    const float* b22  = (const float*)d_in[18];
    const float* Wf1  = (const float*)d_in[19];
    const float* bf1  = (const float*)d_in[20];
    const float* Wf2  = (const float*)d_in[21];
    const float* bf2  = (const float*)d_in[22];

    void *aggr_p, *h1_p, *pool_p;
    cudaGetSymbolAddress(&aggr_p, g_aggr);
    cudaGetSymbolAddress(&h1_p, g_h1);
    cudaGetSymbolAddress(&pool_p, g_pool);
    float4* aggr4 = (float4*)aggr_p;
    float4* h1_4  = (float4*)h1_p;
    float4* pool4 = (float4*)pool_p;
    float*  pool  = (float*)pool_p;

    static bool attr_done = false;
    if (!attr_done) {
        cudaFuncSetAttribute(k_mlp<false>, cudaFuncAttributeMaxDynamicSharedMemorySize, MLP_SMEM);
        cudaFuncSetAttribute(k_mlp<true>,  cudaFuncAttributeMaxDynamicSharedMemorySize, MLP_SMEM);
        attr_done = true;
    }

    const int INIT_BLOCKS = (N_NODES * 16) / 256;            // 6250
    const int EDGE_BLOCKS = N_EDGES / EPB;                   // 6250
    const int MLP_BLOCKS  = (N_NODES + MLP_NPB - 1) / MLP_NPB; // 782

    cudaMemsetAsync(pool_p, 0, N_GRAPHS * 64 * sizeof(float));

    // ---- conv1 ----
    k_init<<<INIT_BLOCKS, 256>>>((const float4*)x, eps1, aggr4);
    k_edge<<<EDGE_BLOCKS, 160>>>((const float4*)x, (const float4*)ea, src, dst,
                                 (const float4*)We1, (const float4*)be1, aggr4);
    k_mlp<false><<<MLP_BLOCKS, 256, MLP_SMEM>>>((const float4*)aggr_p,
                                                (const float4*)W11, (const float4*)b11,
                                                (const float4*)W12, (const float4*)b12,
                                                h1_4, eps2, aggr4, nullptr, nullptr);
    // ---- conv2 ----
    k_edge<<<EDGE_BLOCKS, 160>>>((const float4*)h1_p, (const float4*)ea, src, dst,
                                 (const float4*)We2, (const float4*)be2, aggr4);
    k_mlp<true><<<MLP_BLOCKS, 256, MLP_SMEM>>>((const float4*)aggr_p,
                                               (const float4*)W21, (const float4*)b21,
                                               (const float4*)W22, (const float4*)b22,
                                               nullptr, nullptr, nullptr, bat, pool4);
    // ---- head ----
    k_head<<<1, 128>>>(pool, Wf1, bf1, Wf2, bf2, (float*)d_out);
}